// round 3
// baseline (speedup 1.0000x reference)
#include <cuda_runtime.h>
#include <cuda_bf16.h>
#include <math.h>

// ---------------------------------------------------------------------------
// DiscriptorMatchLoss — sparse cosine matching loss via spatial hashing.
//   mask[i,j,n,m] = ||denorm(ps[i,n]) - denorm(pd[i,j,m])||^2 <= 64
//   out = sum_mask (1 - cos(f[j,n], f[i,m])) / max(count,1)
// Kernel A: blocks 0..B*B-1 bin dst pts of pair (i,j) into smem cells and
//           match src pts against them (pair list append); remaining blocks
//           compute feature row inverse norms.
// Kernel B: 8-lane-per-pair cosine dots (4 pairs per warp, high MLP).
// Kernel C: finalize + reset accumulators for next graph replay.
// ---------------------------------------------------------------------------

#define MAX_ROWS  (1 << 16)
#define MAXC_S    2048          // max grid cells held in smem
#define MAXN_S    2048          // max dst points per (i,j) pair in smem
#define MAX_PAIRS (1 << 20)     // 1M hit-pair slots (expected ~44k)
#define RAD       8.0f
#define RAD2      64.0f

__device__ float    g_invnorm[MAX_ROWS];
__device__ double   g_sum;       // zero-init at load; reset by k_final
__device__ int      g_npairs;    // zero-init at load; reset by k_final
__device__ unsigned g_pairs[MAX_PAIRS];

// ---------------- Kernel A: [bin+match per (i,j)] + [row norms] ------------
__global__ void __launch_bounds__(256)
k_prep(const float* __restrict__ f,
       const float* __restrict__ ps,
       const float* __restrict__ pd,
       const int* __restrict__ hp,
       const int* __restrict__ wp,
       int B, int N, int D, int rows) {
    __shared__ int    s_start[MAXC_S + 1];  // counts -> exclusive starts
    __shared__ int    s_cur[MAXC_S];
    __shared__ float2 s_pts[MAXN_S];
    __shared__ int    s_idx[MAXN_S];
    __shared__ int    s_wsum[8];

    const int tid  = threadIdx.x;
    const int wid  = tid >> 5;
    const int lane = tid & 31;
    const int nBB  = B * B;

    if ((int)blockIdx.x >= nBB) {
        // ---- norms part: one warp per feature row, float4 loads ----
        int w = ((int)blockIdx.x - nBB) * 8 + wid;
        if (w >= rows) return;
        const float4* row = (const float4*)(f + (size_t)w * D);
        int D4 = D >> 2;
        float s = 0.f;
        for (int d = lane; d < D4; d += 32) {
            float4 v = row[d];
            s += v.x * v.x + v.y * v.y + v.z * v.z + v.w * v.w;
        }
        #pragma unroll
        for (int o = 16; o; o >>= 1) s += __shfl_xor_sync(0xffffffffu, s, o);
        if (lane == 0) g_invnorm[w] = rsqrtf(s);
        return;
    }

    // ---- bin + match for pair ij ----
    const int ij = blockIdx.x;
    const int i  = ij / B;
    const int W = wp[0], H = hp[0];

    // pick cell size 2^s >= 16 with ncx*ncy <= MAXC_S
    int s = 4;
    int ncx = ((W - 1) >> s) + 1, ncy = ((H - 1) >> s) + 1;
    while (ncx * ncy > MAXC_S) { s++; ncx = ((W - 1) >> s) + 1; ncy = ((H - 1) >> s) + 1; }
    const int ncells = ncx * ncy;
    const float inv_c = 1.0f / (float)(1 << s);

    const float sx = 0.5f * (float)(W - 1);
    const float sy = 0.5f * (float)(H - 1);

    for (int c = tid; c <= ncells; c += 256) s_start[c] = 0;
    __syncthreads();

    const float2* pdr = (const float2*)(pd + (size_t)ij * N * 2);
    const int npt = (N <= MAXN_S) ? N : MAXN_S;

    // count
    for (int m = tid; m < npt; m += 256) {
        float2 q = pdr[m];
        float x = (q.x + 1.0f) * sx, y = (q.y + 1.0f) * sy;
        int cx = min(ncx - 1, max(0, (int)(x * inv_c)));
        int cy = min(ncy - 1, max(0, (int)(y * inv_c)));
        atomicAdd(&s_start[cy * ncx + cx], 1);
    }
    __syncthreads();

    // exclusive block scan over ncells (counts in s_start, in-place)
    const int chunk = (ncells + 255) / 256;
    const int cb = tid * chunk;
    int tsum = 0;
    for (int k = 0; k < chunk; k++) {
        int c = cb + k;
        if (c < ncells) tsum += s_start[c];
    }
    int v = tsum;
    #pragma unroll
    for (int o = 1; o < 32; o <<= 1) {
        int t = __shfl_up_sync(0xffffffffu, v, o);
        if (lane >= o) v += t;
    }
    if (lane == 31) s_wsum[wid] = v;
    __syncthreads();
    if (tid == 0) {
        int acc = 0;
        #pragma unroll
        for (int t = 0; t < 8; t++) { int x = s_wsum[t]; s_wsum[t] = acc; acc += x; }
    }
    __syncthreads();
    {
        int acc = s_wsum[wid] + v - tsum;   // thread-exclusive prefix
        for (int k = 0; k < chunk; k++) {
            int c = cb + k;
            if (c < ncells) {
                int cnt = s_start[c];
                s_start[c] = acc;
                s_cur[c]   = acc;
                acc += cnt;
            }
        }
    }
    __syncthreads();
    if (tid == 0) s_start[ncells] = npt;

    // scatter
    for (int m = tid; m < npt; m += 256) {
        float2 q = pdr[m];
        float x = (q.x + 1.0f) * sx, y = (q.y + 1.0f) * sy;
        int cx = min(ncx - 1, max(0, (int)(x * inv_c)));
        int cy = min(ncy - 1, max(0, (int)(y * inv_c)));
        int pos = atomicAdd(&s_cur[cy * ncx + cx], 1);
        s_pts[pos] = make_float2(x, y);
        s_idx[pos] = m;
    }
    __syncthreads();

    // ---- match: each thread sweeps src points n = tid, tid+256, ... ----
    const float2* psr = (const float2*)(ps + (size_t)i * N * 2);
    const int iters = (N + 255) / 256;

    for (int it = 0; it < iters; it++) {
        int n = it * 256 + tid;
        unsigned hits[16];
        int hc = 0;
        if (n < N) {
            float2 q = psr[n];
            float x = (q.x + 1.0f) * sx, y = (q.y + 1.0f) * sy;
            int cx0 = max(0, (int)floorf((x - RAD) * inv_c));
            int cx1 = min(ncx - 1, (int)floorf((x + RAD) * inv_c));
            int cy0 = max(0, (int)floorf((y - RAD) * inv_c));
            int cy1 = min(ncy - 1, (int)floorf((y + RAD) * inv_c));
            for (int cy = cy0; cy <= cy1; cy++) {
                for (int cx = cx0; cx <= cx1; cx++) {
                    int cell = cy * ncx + cx;
                    int s0 = s_start[cell], e0 = s_start[cell + 1];
                    for (int k = s0; k < e0; k++) {
                        float2 p = s_pts[k];
                        float dx = p.x - x, dy = p.y - y;
                        if (dx * dx + dy * dy <= RAD2) {
                            unsigned pk = ((unsigned)ij << 24) |
                                          ((unsigned)n << 12) | (unsigned)s_idx[k];
                            if (hc < 16) hits[hc++] = pk;
                            else {
                                int pos = atomicAdd(&g_npairs, 1);
                                if (pos < MAX_PAIRS) g_pairs[pos] = pk;
                            }
                        }
                    }
                }
            }
        }
        // warp-aggregated append (all lanes participate)
        int pre = hc;
        #pragma unroll
        for (int o = 1; o < 32; o <<= 1) {
            int t = __shfl_up_sync(0xffffffffu, pre, o);
            if (lane >= o) pre += t;
        }
        int tot  = __shfl_sync(0xffffffffu, pre, 31);
        int excl = pre - hc;
        if (tot > 0) {
            int bpos = 0;
            if (lane == 31) bpos = atomicAdd(&g_npairs, tot);
            bpos = __shfl_sync(0xffffffffu, bpos, 31);
            for (int k = 0; k < hc; k++) {
                int pos = bpos + excl + k;
                if (pos < MAX_PAIRS) g_pairs[pos] = hits[k];
            }
        }
    }
}

// ---------------- Kernel B: cosine dots, 8 lanes per pair ------------------
__global__ void __launch_bounds__(256)
k_dot(const float* __restrict__ f, int B, int N, int D) {
    const int lane = threadIdx.x & 31;
    const int sub  = lane >> 3;      // pair slot within warp (0..3)
    const int sl   = lane & 7;       // lane within 8-lane group
    const int gw   = (blockIdx.x * blockDim.x + threadIdx.x) >> 5;
    const int nwarp = (gridDim.x * blockDim.x) >> 5;

    int np = g_npairs;
    if (np > MAX_PAIRS) np = MAX_PAIRS;
    const int D4 = D >> 2;

    float lsum = 0.f;
    for (int p0 = gw * 4; p0 < np; p0 += nwarp * 4) {
        int p = p0 + sub;
        bool valid = p < np;
        float dot = 0.f, wgt = 0.f;
        if (valid) {
            unsigned pk = g_pairs[p];
            int ij = pk >> 24;
            int n  = (pk >> 12) & 0xFFF;
            int m  = pk & 0xFFF;
            int i  = ij / B;
            int j  = ij - i * B;
            const float4* fa = (const float4*)(f + ((size_t)j * N + n) * D);
            const float4* fb = (const float4*)(f + ((size_t)i * N + m) * D);
            #pragma unroll 8
            for (int d = sl; d < D4; d += 8) {
                float4 a = fa[d], b = fb[d];
                dot = fmaf(a.x, b.x, fmaf(a.y, b.y, fmaf(a.z, b.z, fmaf(a.w, b.w, dot))));
            }
            wgt = g_invnorm[j * N + n] * g_invnorm[i * N + m];
        }
        dot += __shfl_xor_sync(0xffffffffu, dot, 1);
        dot += __shfl_xor_sync(0xffffffffu, dot, 2);
        dot += __shfl_xor_sync(0xffffffffu, dot, 4);
        if (valid && sl == 0) lsum += 1.0f - dot * wgt;
    }
    #pragma unroll
    for (int o = 16; o; o >>= 1) lsum += __shfl_xor_sync(0xffffffffu, lsum, o);
    if (lane == 0 && lsum != 0.0f) atomicAdd(&g_sum, (double)lsum);
}

// ---------------- Kernel C: finalize + reset for next replay ---------------
__global__ void k_final(float* __restrict__ out) {
    int c = g_npairs;
    if (c < 1) c = 1;
    out[0] = (float)(g_sum / (double)c);
    g_sum = 0.0;
    g_npairs = 0;
}

extern "C" void kernel_launch(void* const* d_in, const int* in_sizes, int n_in,
                              void* d_out, int out_size) {
    const float* features = (const float*)d_in[0];
    const float* pts_src  = (const float*)d_in[1];
    const float* pts_dst  = (const float*)d_in[2];
    const int* hp = (const int*)d_in[4];
    const int* wp = (const int*)d_in[5];
    float* out = (float*)d_out;

    int B = in_sizes[2] / in_sizes[1];
    int N = in_sizes[1] / (2 * B);
    int D = in_sizes[0] / (B * N);
    int rows = B * N;

    int norm_blocks = (rows + 7) / 8;   // one warp per row, 8 warps per block
    k_prep<<<B * B + norm_blocks, 256>>>(features, pts_src, pts_dst, hp, wp,
                                         B, N, D, rows);
    k_dot<<<2048, 256>>>(features, B, N, D);
    k_final<<<1, 1>>>(out);
    (void)n_in; (void)out_size;
}

// round 4
// speedup vs baseline: 2.1240x; 2.1240x over previous
#include <cuda_runtime.h>
#include <cuda_bf16.h>
#include <math.h>

// ---------------------------------------------------------------------------
// DiscriptorMatchLoss — sparse cosine matching loss via bucket spatial hash.
//   mask[i,j,n,m] = ||denorm(ps[i,n]) - denorm(pd[i,j,m])||^2 <= 64
//   out = sum_mask (1 - cos(f[j,n], f[i,m])) / max(count,1)
// K1: chip-wide [bucket-bin all B*B*N dst points] + [feature row inv-norms].
// K2: chip-wide match (1 thread per (i,j,n)) -> compact hit-pair list.
// K3: cosine dots, 8 lanes per pair (4 pairs/warp), block-reduced atomic.
// K4: finalize + reset device state for next graph replay.
// ---------------------------------------------------------------------------

#define MAX_ROWS  (1 << 16)
#define MAXC      2048          // max cells per (i,j) pair
#define MAXIJ     16
#define CAP       32            // bucket capacity (lambda~1.7 => safe)
#define MAX_PAIRS (1 << 20)
#define RAD       8.0f
#define RAD2      64.0f

__device__ float    g_invnorm[MAX_ROWS];
__device__ double   g_sum;                      // reset by k_final
__device__ int      g_npairs;                   // reset by k_final
__device__ int      g_ccnt[MAXIJ * MAXC];       // bucket counts, reset by k_final
__device__ float2   g_cpts[MAXIJ * MAXC * CAP]; // denormalized dst points
__device__ int      g_cidx[MAXIJ * MAXC * CAP]; // dst point index m
__device__ unsigned g_pairs[MAX_PAIRS];

__device__ __forceinline__ void grid_shape(int W, int H, int& s, int& ncx, int& ncy) {
    s = 4;
    ncx = ((W - 1) >> s) + 1; ncy = ((H - 1) >> s) + 1;
    while (ncx * ncy > MAXC) { s++; ncx = ((W - 1) >> s) + 1; ncy = ((H - 1) >> s) + 1; }
}

// ---------------- K1: bucket-bin dst points + row norms --------------------
__global__ void __launch_bounds__(256)
k_bin_norms(const float* __restrict__ f,
            const float* __restrict__ pd,
            const int* __restrict__ hp,
            const int* __restrict__ wp,
            int B, int N, int D, int rows, int binBlocks) {
    const int tid  = threadIdx.x;
    const int lane = tid & 31;

    if ((int)blockIdx.x < binBlocks) {
        // bin: one thread per (ij, m)
        int t = blockIdx.x * 256 + tid;
        int total = B * B * N;
        if (t >= total) return;
        int ij = t / N;
        int W = wp[0], H = hp[0];
        int s, ncx, ncy; grid_shape(W, H, s, ncx, ncy);
        float inv_c = 1.0f / (float)(1 << s);
        float sx = 0.5f * (float)(W - 1), sy = 0.5f * (float)(H - 1);

        float2 q = ((const float2*)pd)[t];
        float x = (q.x + 1.0f) * sx, y = (q.y + 1.0f) * sy;
        int cx = min(ncx - 1, max(0, (int)(x * inv_c)));
        int cy = min(ncy - 1, max(0, (int)(y * inv_c)));
        int cell = ij * MAXC + cy * ncx + cx;
        int slot = atomicAdd(&g_ccnt[cell], 1);
        if (slot < CAP) {
            g_cpts[cell * CAP + slot] = make_float2(x, y);
            g_cidx[cell * CAP + slot] = t % N;
        }
        return;
    }

    // norms: one warp per feature row
    int w = ((int)blockIdx.x - binBlocks) * 8 + (tid >> 5);
    if (w >= rows) return;
    const float4* row = (const float4*)(f + (size_t)w * D);
    int D4 = D >> 2;
    float s = 0.f;
    for (int d = lane; d < D4; d += 32) {
        float4 v = row[d];
        s += v.x * v.x + v.y * v.y + v.z * v.z + v.w * v.w;
    }
    #pragma unroll
    for (int o = 16; o; o >>= 1) s += __shfl_xor_sync(0xffffffffu, s, o);
    if (lane == 0) g_invnorm[w] = rsqrtf(s);
}

// ---------------- K2: match (1 thread per (i,j,n)) -------------------------
__global__ void __launch_bounds__(256)
k_match(const float* __restrict__ ps,
        const int* __restrict__ hp,
        const int* __restrict__ wp,
        int B, int N) {
    const int t    = blockIdx.x * 256 + threadIdx.x;
    const int lane = threadIdx.x & 31;
    const int total = B * B * N;

    unsigned hits[16];
    int hc = 0;

    if (t < total) {
        int n  = t % N;
        int ij = t / N;
        int i  = ij / B;
        int W = wp[0], H = hp[0];
        int s, ncx, ncy; grid_shape(W, H, s, ncx, ncy);
        float inv_c = 1.0f / (float)(1 << s);
        float sx = 0.5f * (float)(W - 1), sy = 0.5f * (float)(H - 1);

        float2 q = ((const float2*)ps)[(size_t)i * N + n];
        float x = (q.x + 1.0f) * sx, y = (q.y + 1.0f) * sy;
        int cx0 = max(0, (int)floorf((x - RAD) * inv_c));
        int cx1 = min(ncx - 1, (int)floorf((x + RAD) * inv_c));
        int cy0 = max(0, (int)floorf((y - RAD) * inv_c));
        int cy1 = min(ncy - 1, (int)floorf((y + RAD) * inv_c));

        for (int cy = cy0; cy <= cy1; cy++) {
            for (int cx = cx0; cx <= cx1; cx++) {
                int cell = ij * MAXC + cy * ncx + cx;
                int cnt = g_ccnt[cell];
                if (cnt > CAP) cnt = CAP;
                const float2* cp = g_cpts + (size_t)cell * CAP;
                const int*    ci = g_cidx + (size_t)cell * CAP;
                for (int k = 0; k < cnt; k++) {
                    float2 p = cp[k];
                    float dx = p.x - x, dy = p.y - y;
                    if (dx * dx + dy * dy <= RAD2) {
                        unsigned pk = ((unsigned)ij << 24) |
                                      ((unsigned)n << 12) | (unsigned)ci[k];
                        if (hc < 16) hits[hc++] = pk;
                        else {
                            int pos = atomicAdd(&g_npairs, 1);
                            if (pos < MAX_PAIRS) g_pairs[pos] = pk;
                        }
                    }
                }
            }
        }
    }

    // warp-aggregated append
    int pre = hc;
    #pragma unroll
    for (int o = 1; o < 32; o <<= 1) {
        int v = __shfl_up_sync(0xffffffffu, pre, o);
        if (lane >= o) pre += v;
    }
    int tot  = __shfl_sync(0xffffffffu, pre, 31);
    int excl = pre - hc;
    if (tot > 0) {
        int bpos = 0;
        if (lane == 31) bpos = atomicAdd(&g_npairs, tot);
        bpos = __shfl_sync(0xffffffffu, bpos, 31);
        for (int k = 0; k < hc; k++) {
            int pos = bpos + excl + k;
            if (pos < MAX_PAIRS) g_pairs[pos] = hits[k];
        }
    }
}

// ---------------- K3: cosine dots, 8 lanes per pair ------------------------
__global__ void __launch_bounds__(256)
k_dot(const float* __restrict__ f, int B, int N, int D) {
    __shared__ float s_red[8];
    const int tid   = threadIdx.x;
    const int lane  = tid & 31;
    const int wid   = tid >> 5;
    const int sub   = lane >> 3;
    const int sl    = lane & 7;
    const int gw    = (blockIdx.x * 256 + tid) >> 5;
    const int nwarp = (gridDim.x * 256) >> 5;

    int np = g_npairs;
    if (np > MAX_PAIRS) np = MAX_PAIRS;
    const int D4 = D >> 2;

    float lsum = 0.f;
    for (int p0 = gw * 4; p0 < np; p0 += nwarp * 4) {
        int p = p0 + sub;
        bool valid = p < np;
        float dot = 0.f, wgt = 0.f;
        if (valid) {
            unsigned pk = g_pairs[p];
            int ij = pk >> 24;
            int n  = (pk >> 12) & 0xFFF;
            int m  = pk & 0xFFF;
            int i  = ij / B;
            int j  = ij - i * B;
            const float4* fa = (const float4*)(f + ((size_t)j * N + n) * D);
            const float4* fb = (const float4*)(f + ((size_t)i * N + m) * D);
            #pragma unroll 8
            for (int d = sl; d < D4; d += 8) {
                float4 a = fa[d], b = fb[d];
                dot = fmaf(a.x, b.x, fmaf(a.y, b.y, fmaf(a.z, b.z, fmaf(a.w, b.w, dot))));
            }
            wgt = g_invnorm[j * N + n] * g_invnorm[i * N + m];
        }
        dot += __shfl_xor_sync(0xffffffffu, dot, 1);
        dot += __shfl_xor_sync(0xffffffffu, dot, 2);
        dot += __shfl_xor_sync(0xffffffffu, dot, 4);
        if (valid && sl == 0) lsum += 1.0f - dot * wgt;
    }
    // warp reduce -> block reduce -> 1 global atomic per block
    #pragma unroll
    for (int o = 16; o; o >>= 1) lsum += __shfl_xor_sync(0xffffffffu, lsum, o);
    if (lane == 0) s_red[wid] = lsum;
    __syncthreads();
    if (wid == 0) {
        float v = (lane < 8) ? s_red[lane] : 0.f;
        #pragma unroll
        for (int o = 4; o; o >>= 1) v += __shfl_xor_sync(0xffffffffu, v, o);
        if (lane == 0 && v != 0.f) atomicAdd(&g_sum, (double)v);
    }
}

// ---------------- K4: finalize + reset state for next replay ---------------
__global__ void k_final(float* __restrict__ out, int B) {
    int tid = threadIdx.x;
    if (tid == 0) {
        int c = g_npairs;
        if (c < 1) c = 1;
        out[0] = (float)(g_sum / (double)c);
    }
    __syncthreads();
    if (tid == 0) { g_sum = 0.0; g_npairs = 0; }
    int ncnt = B * B * MAXC;
    for (int c = tid; c < ncnt; c += blockDim.x) g_ccnt[c] = 0;
}

extern "C" void kernel_launch(void* const* d_in, const int* in_sizes, int n_in,
                              void* d_out, int out_size) {
    const float* features = (const float*)d_in[0];
    const float* pts_src  = (const float*)d_in[1];
    const float* pts_dst  = (const float*)d_in[2];
    const int* hp = (const int*)d_in[4];
    const int* wp = (const int*)d_in[5];
    float* out = (float*)d_out;

    int B = in_sizes[2] / in_sizes[1];
    int N = in_sizes[1] / (2 * B);
    int D = in_sizes[0] / (B * N);
    int rows = B * N;

    int binBlocks  = (B * B * N + 255) / 256;   // 128
    int normBlocks = (rows + 7) / 8;            // 1024
    k_bin_norms<<<binBlocks + normBlocks, 256>>>(features, pts_dst, hp, wp,
                                                 B, N, D, rows, binBlocks);
    k_match<<<(B * B * N + 255) / 256, 256>>>(pts_src, hp, wp, B, N);
    k_dot<<<2048, 256>>>(features, B, N, D);
    k_final<<<1, 1024>>>(out, B);
    (void)n_in; (void)out_size;
}